// round 14
// baseline (speedup 1.0000x reference)
#include <cuda_runtime.h>
#include <math.h>

#define C     32000
#define C4    8000      // C / 4
#define CS4   6000      // float4s resident in smem (24000 floats = 96000 B)
#define NT    1024      // threads per block
#define NW    (NT / 32) // warps per block

__global__ __launch_bounds__(NT, 2)
void post_54795192762798_kernel(const float* __restrict__ x,
                                const float* __restrict__ u,
                                const float* __restrict__ noise,
                                float* __restrict__ out) {
    extern __shared__ float s[];          // CS4*4 floats = 96000 bytes (holds e)
    __shared__ float red_v[NW];
    __shared__ int   red_i[NW];
    __shared__ float b_m;                 // broadcast row max of x
    __shared__ int   b_idx;               // broadcast argmax
    __shared__ float b_inv;               // broadcast 1/sum

    const int row  = blockIdx.x;
    const int tid  = threadIdx.x;
    const int lane = tid & 31;
    const int wid  = tid >> 5;

    const float4* x4 = (const float4*)(x     + (size_t)row * C);
    const float4* u4 = (const float4*)(u     + (size_t)row * C);
    const float4* n4 = (const float4*)(noise + (size_t)row * C);
    float4*       o4 = (float4*)      (out   + (size_t)row * C);
    float4*       s4 = (float4*)s;

    // ------- pass 1: max + argmax of x, software double-buffered -------------
    float best = -INFINITY;
    int   bi   = 0x7fffffff;
    {
        int i = tid;
        float4 v = x4[i];                 // every tid < NT has i = tid < C4
        for (;;) {
            if (i + NT < C4) {
                float4 vn = x4[i + NT];   // prefetch next while consuming v
                int base = i * 4;
                if (v.x > best) { best = v.x; bi = base;     }
                if (v.y > best) { best = v.y; bi = base + 1; }
                if (v.z > best) { best = v.z; bi = base + 2; }
                if (v.w > best) { best = v.w; bi = base + 3; }
                v = vn; i += NT;
            } else {
                int base = i * 4;
                if (v.x > best) { best = v.x; bi = base;     }
                if (v.y > best) { best = v.y; bi = base + 1; }
                if (v.z > best) { best = v.z; bi = base + 2; }
                if (v.w > best) { best = v.w; bi = base + 3; }
                break;
            }
        }
    }
    #pragma unroll
    for (int o = 16; o; o >>= 1) {
        float ov = __shfl_down_sync(0xffffffffu, best, o);
        int   oi = __shfl_down_sync(0xffffffffu, bi,   o);
        if (ov > best || (ov == best && oi < bi)) { best = ov; bi = oi; }
    }
    if (lane == 0) { red_v[wid] = best; red_i[wid] = bi; }
    __syncthreads();
    if (wid == 0) {
        best = (lane < NW) ? red_v[lane] : -INFINITY;
        bi   = (lane < NW) ? red_i[lane] : 0x7fffffff;
        #pragma unroll
        for (int o = 16; o; o >>= 1) {
            float ov = __shfl_down_sync(0xffffffffu, best, o);
            int   oi = __shfl_down_sync(0xffffffffu, bi,   o);
            if (ov > best || (ov == best && oi < bi)) { best = ov; bi = oi; }
        }
        if (lane == 0) { b_m = best; b_idx = bi; }
    }
    __syncthreads();
    const float m    = b_m;
    const int   amax = b_idx;

    // e = exp(x2 - m), x2 = (0.1+0.2u)*m + noise (argmax lane: m+noise).
    // m = max(x) is a valid stabilizer (softmax shift-invariance); |x2-m| is
    // O(10) for this N(0,1)/U(0,1) data so fp32 exp/sum are safe.
    #define COMPUTE_E(v, uu, nn, i)                                           \
        do {                                                                  \
            (v).x = fmaf(fmaf(0.2f, (uu).x, 0.1f), m, (nn).x) - m;            \
            (v).y = fmaf(fmaf(0.2f, (uu).y, 0.1f), m, (nn).y) - m;            \
            (v).z = fmaf(fmaf(0.2f, (uu).z, 0.1f), m, (nn).z) - m;            \
            (v).w = fmaf(fmaf(0.2f, (uu).w, 0.1f), m, (nn).w) - m;            \
            int d_ = amax - (i) * 4;                                          \
            if (d_ >= 0 && d_ < 4) {                                          \
                float nv_ = (d_ == 0) ? (nn).x : (d_ == 1) ? (nn).y :         \
                            (d_ == 2) ? (nn).z : (nn).w;                      \
                if (d_ == 0) (v).x = nv_;                                     \
                else if (d_ == 1) (v).y = nv_;                                \
                else if (d_ == 2) (v).z = nv_;                                \
                else (v).w = nv_;                                             \
            }                                                                 \
            (v).x = __expf((v).x);                                            \
            (v).y = __expf((v).y);                                            \
            (v).z = __expf((v).z);                                            \
            (v).w = __expf((v).w);                                            \
        } while (0)

    // ------- pass 2: stream u,noise -> e (double-buffered); sum --------------
    float sum = 0.0f;
    {
        int i = tid;
        float4 uu = u4[i];
        float4 nn = n4[i];
        for (;;) {
            if (i + NT < C4) {
                float4 uu_n = u4[i + NT]; // prefetch next pair while computing
                float4 nn_n = n4[i + NT];
                float4 v;
                COMPUTE_E(v, uu, nn, i);
                if (i < CS4) s4[i] = v;
                sum += (v.x + v.y) + (v.z + v.w);
                uu = uu_n; nn = nn_n; i += NT;
            } else {
                float4 v;
                COMPUTE_E(v, uu, nn, i);
                if (i < CS4) s4[i] = v;
                sum += (v.x + v.y) + (v.z + v.w);
                break;
            }
        }
    }
    #pragma unroll
    for (int o = 16; o; o >>= 1)
        sum += __shfl_down_sync(0xffffffffu, sum, o);
    if (lane == 0) red_v[wid] = sum;
    __syncthreads();
    if (wid == 0) {
        sum = (lane < NW) ? red_v[lane] : 0.0f;
        #pragma unroll
        for (int o = 16; o; o >>= 1)
            sum += __shfl_down_sync(0xffffffffu, sum, o);
        if (lane == 0) b_inv = 1.0f / sum;
    }
    __syncthreads();
    const float inv = b_inv;

    // ---------------- pass 3: out = e * inv ----------------------------------
    for (int i = tid; i < CS4; i += NT) {
        float4 v = s4[i];
        v.x *= inv; v.y *= inv; v.z *= inv; v.w *= inv;
        __stcs(o4 + i, v);                // evict-first: out never re-read
    }
    for (int i = CS4 + tid; i < C4; i += NT) {
        float4 uu = u4[i];                // L2 hit (read moments ago in pass 2)
        float4 nn = n4[i];
        float4 v;
        COMPUTE_E(v, uu, nn, i);
        v.x *= inv; v.y *= inv; v.z *= inv; v.w *= inv;
        __stcs(o4 + i, v);
    }
    #undef COMPUTE_E
}

extern "C" void kernel_launch(void* const* d_in, const int* in_sizes, int n_in,
                              void* d_out, int out_size) {
    const float* x     = (const float*)d_in[0];
    const float* u     = (const float*)d_in[1];
    const float* noise = (const float*)d_in[2];
    float* out = (float*)d_out;

    const int rows = in_sizes[0] / C;                 // 2048
    const int smem = CS4 * 4 * (int)sizeof(float);    // 96000 bytes

    cudaFuncSetAttribute(post_54795192762798_kernel,
                         cudaFuncAttributeMaxDynamicSharedMemorySize, smem);

    post_54795192762798_kernel<<<rows, NT, smem>>>(x, u, noise, out);
}

// round 16
// speedup vs baseline: 1.0345x; 1.0345x over previous
#include <cuda_runtime.h>
#include <math.h>

#define C     32000
#define C4    8000      // C / 4
#define CS4   6000      // float4s resident in smem (24000 floats = 96000 B)
#define NT    1024      // kernel B threads per block
#define NW    (NT / 32)
#define NTA   128       // kernel A threads per block
#define NWA   (NTA / 32)
#define ROWS  2048

__device__ float g_m[ROWS];
__device__ int   g_amax[ROWS];

// ---------------- kernel A: per-row max + argmax of x ------------------------
__global__ __launch_bounds__(NTA, 16)
void rowmax_kernel(const float* __restrict__ x) {
    __shared__ float rv[NWA];
    __shared__ int   ri[NWA];

    const int row  = blockIdx.x;
    const int tid  = threadIdx.x;
    const int lane = tid & 31;
    const int wid  = tid >> 5;

    const float4* x4 = (const float4*)(x + (size_t)row * C);

    float best = -INFINITY;
    int   bi   = 0x7fffffff;
    for (int i = tid; i < C4; i += NTA) {
        float4 v = x4[i];
        int base = i * 4;
        if (v.x > best) { best = v.x; bi = base;     }
        if (v.y > best) { best = v.y; bi = base + 1; }
        if (v.z > best) { best = v.z; bi = base + 2; }
        if (v.w > best) { best = v.w; bi = base + 3; }
    }
    #pragma unroll
    for (int o = 16; o; o >>= 1) {
        float ov = __shfl_down_sync(0xffffffffu, best, o);
        int   oi = __shfl_down_sync(0xffffffffu, bi,   o);
        if (ov > best || (ov == best && oi < bi)) { best = ov; bi = oi; }
    }
    if (lane == 0) { rv[wid] = best; ri[wid] = bi; }
    __syncthreads();
    if (tid == 0) {
        best = rv[0]; bi = ri[0];
        #pragma unroll
        for (int w = 1; w < NWA; w++) {
            if (rv[w] > best || (rv[w] == best && ri[w] < bi)) {
                best = rv[w]; bi = ri[w];
            }
        }
        g_m[row]    = best;
        g_amax[row] = bi;
    }
}

// ---------------- kernel B: e = exp(x2 - m); softmax -------------------------
__global__ __launch_bounds__(NT, 2)
void post_54795192762798_kernel(const float* __restrict__ u,
                                const float* __restrict__ noise,
                                float* __restrict__ out) {
    extern __shared__ float s[];          // CS4*4 floats = 96000 bytes (holds e)
    __shared__ float red_v[NW];
    __shared__ float b_inv;               // broadcast 1/sum

    const int row  = blockIdx.x;
    const int tid  = threadIdx.x;
    const int lane = tid & 31;
    const int wid  = tid >> 5;

    const float4* u4 = (const float4*)(u     + (size_t)row * C);
    const float4* n4 = (const float4*)(noise + (size_t)row * C);
    float4*       o4 = (float4*)      (out   + (size_t)row * C);
    float4*       s4 = (float4*)s;

    const float m    = g_m[row];          // broadcast load (L2/L1 hit)
    const int   amax = g_amax[row];

    // e = exp(x2 - m), x2 = (0.1+0.2u)*m + noise (argmax lane: m+noise).
    // m = max(x) is a valid stabilizer (softmax shift-invariance); |x2-m| is
    // O(10) for this N(0,1)/U(0,1) data so fp32 exp/sum are safe.
    #define COMPUTE_E(v, uu, nn, i)                                           \
        do {                                                                  \
            (v).x = fmaf(fmaf(0.2f, (uu).x, 0.1f), m, (nn).x) - m;            \
            (v).y = fmaf(fmaf(0.2f, (uu).y, 0.1f), m, (nn).y) - m;            \
            (v).z = fmaf(fmaf(0.2f, (uu).z, 0.1f), m, (nn).z) - m;            \
            (v).w = fmaf(fmaf(0.2f, (uu).w, 0.1f), m, (nn).w) - m;            \
            int d_ = amax - (i) * 4;                                          \
            if (d_ >= 0 && d_ < 4) {                                          \
                float nv_ = (d_ == 0) ? (nn).x : (d_ == 1) ? (nn).y :         \
                            (d_ == 2) ? (nn).z : (nn).w;                      \
                if (d_ == 0) (v).x = nv_;                                     \
                else if (d_ == 1) (v).y = nv_;                                \
                else if (d_ == 2) (v).z = nv_;                                \
                else (v).w = nv_;                                             \
            }                                                                 \
            (v).x = __expf((v).x);                                            \
            (v).y = __expf((v).y);                                            \
            (v).z = __expf((v).z);                                            \
            (v).w = __expf((v).w);                                            \
        } while (0)

    // ------- pass 1: stream u,noise -> e; smem for i<CS4; accumulate sum -----
    float sum = 0.0f;
    for (int i = tid; i < CS4; i += NT) {
        float4 uu = u4[i];
        float4 nn = n4[i];
        float4 v;
        COMPUTE_E(v, uu, nn, i);
        s4[i] = v;
        sum += (v.x + v.y) + (v.z + v.w);
    }
    for (int i = CS4 + tid; i < C4; i += NT) {
        float4 uu = u4[i];
        float4 nn = n4[i];
        float4 v;
        COMPUTE_E(v, uu, nn, i);
        sum += (v.x + v.y) + (v.z + v.w);
    }
    #pragma unroll
    for (int o = 16; o; o >>= 1)
        sum += __shfl_down_sync(0xffffffffu, sum, o);
    if (lane == 0) red_v[wid] = sum;
    __syncthreads();
    if (wid == 0) {
        sum = (lane < NW) ? red_v[lane] : 0.0f;
        #pragma unroll
        for (int o = 16; o; o >>= 1)
            sum += __shfl_down_sync(0xffffffffu, sum, o);
        if (lane == 0) b_inv = 1.0f / sum;
    }
    __syncthreads();
    const float inv = b_inv;

    // ---------------- pass 2: out = e * inv ----------------------------------
    for (int i = tid; i < CS4; i += NT) {
        float4 v = s4[i];
        v.x *= inv; v.y *= inv; v.z *= inv; v.w *= inv;
        __stcs(o4 + i, v);                // evict-first: out never re-read
    }
    for (int i = CS4 + tid; i < C4; i += NT) {
        float4 uu = u4[i];                // L2 hit (read moments ago in pass 1)
        float4 nn = n4[i];
        float4 v;
        COMPUTE_E(v, uu, nn, i);
        v.x *= inv; v.y *= inv; v.z *= inv; v.w *= inv;
        __stcs(o4 + i, v);
    }
    #undef COMPUTE_E
}

extern "C" void kernel_launch(void* const* d_in, const int* in_sizes, int n_in,
                              void* d_out, int out_size) {
    const float* x     = (const float*)d_in[0];
    const float* u     = (const float*)d_in[1];
    const float* noise = (const float*)d_in[2];
    float* out = (float*)d_out;

    const int rows = in_sizes[0] / C;                 // 2048
    const int smem = CS4 * 4 * (int)sizeof(float);    // 96000 bytes

    cudaFuncSetAttribute(post_54795192762798_kernel,
                         cudaFuncAttributeMaxDynamicSharedMemorySize, smem);

    rowmax_kernel<<<rows, NTA>>>(x);
    post_54795192762798_kernel<<<rows, NT, smem>>>(u, noise, out);
}